// round 15
// baseline (speedup 1.0000x reference)
#include <cuda_runtime.h>
#include <cuda_bf16.h>
#include <cstdint>

#define D_MODEL 2048
#define N_HEADS 32
#define HEAD_DIM 64
#define TT 8
#define MROWS 256
#define CACHE_T 1016
#define SEQ 1024
#define DD (D_MODEL * D_MODEL)

// ---------------- scratch ----------------
__device__ float g_q[MROWS * D_MODEL];
__device__ float g_k[MROWS * D_MODEL];
__device__ float g_v[MROWS * D_MODEL];
__device__ float g_ao[MROWS * D_MODEL];
__device__ float g_part[4 * MROWS * D_MODEL];

// bf16 hi/lo planes (pre-converted)
__device__ __align__(128) __nv_bfloat16 g_wh[4 * DD];
__device__ __align__(128) __nv_bfloat16 g_wl[4 * DD];
__device__ __align__(128) __nv_bfloat16 g_xh[MROWS * D_MODEL];
__device__ __align__(128) __nv_bfloat16 g_xl[MROWS * D_MODEL];
__device__ __align__(128) __nv_bfloat16 g_aoh[MROWS * D_MODEL];
__device__ __align__(128) __nv_bfloat16 g_aol[MROWS * D_MODEL];

#define CSLAB (MROWS * D_MODEL)

// ---------------- common helpers ----------------
#define MMA_BF16(d, a0, a1, a2, a3, b0, b1)                                      \
    asm volatile("mma.sync.aligned.m16n8k16.row.col.f32.bf16.bf16.f32 "          \
                 "{%0,%1,%2,%3}, {%4,%5,%6,%7}, {%8,%9}, {%0,%1,%2,%3};\n"       \
                 : "+f"(d[0]), "+f"(d[1]), "+f"(d[2]), "+f"(d[3])                \
                 : "r"(a0), "r"(a1), "r"(a2), "r"(a3), "r"(b0), "r"(b1))

#define LDSM4(r0, r1, r2, r3, addr)                                              \
    asm volatile("ldmatrix.sync.aligned.m8n8.x4.shared.b16 {%0,%1,%2,%3}, [%4];" \
                 : "=r"(r0), "=r"(r1), "=r"(r2), "=r"(r3) : "r"(addr))

__device__ __forceinline__ void f2_hilo(float2 f, uint32_t& hi, uint32_t& lo)
{
    __nv_bfloat162 h = __floats2bfloat162_rn(f.x, f.y);
    float2 hf = __bfloat1622float2(h);
    __nv_bfloat162 l = __floats2bfloat162_rn(f.x - hf.x, f.y - hf.y);
    hi = *reinterpret_cast<uint32_t*>(&h);
    lo = *reinterpret_cast<uint32_t*>(&l);
}

#define CP_COMMIT asm volatile("cp.async.commit_group;\n" ::: "memory")

__device__ __forceinline__ void cp16(uint32_t dst, const void* src)
{
    asm volatile("cp.async.cg.shared.global [%0], [%1], 16;\n" ::"r"(dst), "l"(src));
}

// ---------------- conversion: fp32 -> bf16 hi/lo planes ----------------
__device__ __forceinline__ void conv_body(const float* __restrict__ src,
                                          __nv_bfloat16* __restrict__ dh,
                                          __nv_bfloat16* __restrict__ dl, int n4)
{
    for (int i = blockIdx.x * blockDim.x + threadIdx.x; i < n4; i += gridDim.x * blockDim.x) {
        float4 v = reinterpret_cast<const float4*>(src)[i];
        __nv_bfloat162 h01 = __floats2bfloat162_rn(v.x, v.y);
        __nv_bfloat162 h23 = __floats2bfloat162_rn(v.z, v.w);
        float2 f01 = __bfloat1622float2(h01);
        float2 f23 = __bfloat1622float2(h23);
        __nv_bfloat162 l01 = __floats2bfloat162_rn(v.x - f01.x, v.y - f01.y);
        __nv_bfloat162 l23 = __floats2bfloat162_rn(v.z - f23.x, v.w - f23.y);
        uint2 h, l;
        h.x = *reinterpret_cast<uint32_t*>(&h01);
        h.y = *reinterpret_cast<uint32_t*>(&h23);
        l.x = *reinterpret_cast<uint32_t*>(&l01);
        l.y = *reinterpret_cast<uint32_t*>(&l23);
        reinterpret_cast<uint2*>(dh)[i] = h;
        reinterpret_cast<uint2*>(dl)[i] = l;
    }
}

__global__ __launch_bounds__(256) void conv_split(
    const float* __restrict__ Wq, const float* __restrict__ Wk,
    const float* __restrict__ Wv, const float* __restrict__ Wo,
    const float* __restrict__ x)
{
    const int z = blockIdx.y;
    if (z < 4) {
        const float* src = (z == 0) ? Wq : (z == 1) ? Wk : (z == 2) ? Wv : Wo;
        conv_body(src, g_wh + (size_t)z * DD, g_wl + (size_t)z * DD, DD / 4);
    } else {
        conv_body(x, g_xh, g_xl, MROWS * D_MODEL / 4);
    }
}

__global__ __launch_bounds__(256) void conv_ao()
{
    conv_body(g_ao, g_aoh, g_aol, MROWS * D_MODEL / 4);
}

// ---------------- GEMM: pure bf16, 4-stage cp.async, 128x128 tile ----------------
#define GBK 32
#define KST 40
#define PLB (128 * KST * 2)               // plane bytes = 10240
#define GEMM_SMEM (4 * 4 * PLB)           // 163840

__global__ __launch_bounds__(512) void gemm_bf16(
    int mode,
    const float* __restrict__ bq, const float* __restrict__ bk, const float* __restrict__ bv)
{
    extern __shared__ char gsm[];
    const uint32_t smb = (uint32_t)__cvta_generic_to_shared(gsm);

    const int z = blockIdx.z;
    const __nv_bfloat16* Ah_g = mode ? g_aoh : g_xh;
    const __nv_bfloat16* Al_g = mode ? g_aol : g_xl;
    const int wsel = mode ? 3 : z;
    const __nv_bfloat16* Bh_g = g_wh + (size_t)wsel * DD;
    const __nv_bfloat16* Bl_g = g_wl + (size_t)wsel * DD;
    float* C = mode ? (g_part + (size_t)z * CSLAB)
                    : ((z == 0) ? g_q : (z == 1) ? g_k : g_v);
    const float* bias = (z == 0) ? bq : (z == 1) ? bk : bv;

    const int kt0 = mode ? z * 16 : 0;
    const int NT = mode ? 16 : 64;

    const int m0 = blockIdx.y * 128;
    const int n0 = blockIdx.x * 128;
    const int tid = threadIdx.x;
    const int lane = tid & 31, wid = tid >> 5;
    const int wm = (wid & 3) * 32;
    const int wn = (wid >> 2) * 32;

    float c[2][4][4];
#pragma unroll
    for (int i = 0; i < 2; i++)
#pragma unroll
        for (int j = 0; j < 4; j++)
#pragma unroll
            for (int e = 0; e < 4; e++) c[i][j][e] = 0.0f;

    const int arow = wm + (lane & 15);
    const int akof = (lane >> 4) * 8;
    const int brow_base = wn + ((lane >> 4) * 8) + (lane & 7);
    const int bkof = ((lane >> 3) & 1) * 8;

    // cp.async mapping: thread -> (row, chunk); plane = h of 4 issues
    const int cr = tid >> 2;              // 0..127
    const int cc = (tid & 3) * 8;         // bf16 elem offset within 32-k chunk

    auto issue = [&](int kt, int s) {
        const uint32_t stg = smb + (uint32_t)(s * 4 * PLB);
        const int k0 = kt * GBK;
        const uint32_t doff = (uint32_t)(cr * KST + cc) * 2;
        cp16(stg + 0 * PLB + doff, Ah_g + (size_t)(m0 + cr) * D_MODEL + k0 + cc);
        cp16(stg + 1 * PLB + doff, Al_g + (size_t)(m0 + cr) * D_MODEL + k0 + cc);
        cp16(stg + 2 * PLB + doff, Bh_g + (size_t)(n0 + cr) * D_MODEL + k0 + cc);
        cp16(stg + 3 * PLB + doff, Bl_g + (size_t)(n0 + cr) * D_MODEL + k0 + cc);
    };

#pragma unroll
    for (int s = 0; s < 3; s++) {
        issue(kt0 + s, s);
        CP_COMMIT;
    }

    for (int it = 0; it < NT; it++) {
        const int rem = NT - 1 - it;
        if (rem >= 2)      asm volatile("cp.async.wait_group 2;\n" ::: "memory");
        else if (rem == 1) asm volatile("cp.async.wait_group 1;\n" ::: "memory");
        else               asm volatile("cp.async.wait_group 0;\n" ::: "memory");
        __syncthreads();
        if (it + 3 < NT) {
            issue(kt0 + it + 3, (it + 3) & 3);
            CP_COMMIT;
        }

        const uint32_t stg = smb + (uint32_t)((it & 3) * 4 * PLB);
        const uint32_t a_h = stg;
        const uint32_t a_l = stg + PLB;
        const uint32_t b_h = stg + 2 * PLB;
        const uint32_t b_l = stg + 3 * PLB;

#pragma unroll
        for (int ks = 0; ks < GBK; ks += 16) {
            uint32_t ah[2][4], al[2][4], bh[4][2], bl[4][2];
#pragma unroll
            for (int i = 0; i < 2; i++) {
                uint32_t off = (uint32_t)(((arow + i * 16) * KST + ks + akof) * 2);
                LDSM4(ah[i][0], ah[i][1], ah[i][2], ah[i][3], a_h + off);
                LDSM4(al[i][0], al[i][1], al[i][2], al[i][3], a_l + off);
            }
#pragma unroll
            for (int jp = 0; jp < 2; jp++) {
                uint32_t off = (uint32_t)(((brow_base + jp * 16) * KST + ks + bkof) * 2);
                LDSM4(bh[jp * 2][0], bh[jp * 2][1], bh[jp * 2 + 1][0], bh[jp * 2 + 1][1], b_h + off);
                LDSM4(bl[jp * 2][0], bl[jp * 2][1], bl[jp * 2 + 1][0], bl[jp * 2 + 1][1], b_l + off);
            }
#pragma unroll
            for (int i = 0; i < 2; i++)
#pragma unroll
                for (int j = 0; j < 4; j++)
                    MMA_BF16(c[i][j], ah[i][0], ah[i][1], ah[i][2], ah[i][3], bh[j][0], bh[j][1]);
#pragma unroll
            for (int i = 0; i < 2; i++)
#pragma unroll
                for (int j = 0; j < 4; j++)
                    MMA_BF16(c[i][j], ah[i][0], ah[i][1], ah[i][2], ah[i][3], bl[j][0], bl[j][1]);
#pragma unroll
            for (int i = 0; i < 2; i++)
#pragma unroll
                for (int j = 0; j < 4; j++)
                    MMA_BF16(c[i][j], al[i][0], al[i][1], al[i][2], al[i][3], bh[j][0], bh[j][1]);
        }
    }

#pragma unroll
    for (int i = 0; i < 2; i++)
#pragma unroll
        for (int j = 0; j < 4; j++) {
            int row = m0 + wm + i * 16 + (lane >> 2);
            int col = n0 + wn + j * 8 + (lane & 3) * 2;
            float b0 = 0.f, b1 = 0.f;
            if (!mode) { b0 = bias[col]; b1 = bias[col + 1]; }
            C[(size_t)row * D_MODEL + col]           = c[i][j][0] + b0;
            C[(size_t)row * D_MODEL + col + 1]       = c[i][j][1] + b1;
            C[(size_t)(row + 8) * D_MODEL + col]     = c[i][j][2] + b0;
            C[(size_t)(row + 8) * D_MODEL + col + 1] = c[i][j][3] + b1;
        }
}

// ---------------- O split-K reduce ----------------
__global__ __launch_bounds__(256) void reduce_o(const float* __restrict__ bo, float* __restrict__ out)
{
    size_t base = ((size_t)blockIdx.x * 256 + threadIdx.x) * 4;
    int col = (int)(base & (D_MODEL - 1));
    float4 a = *(const float4*)(g_part + 0 * (size_t)CSLAB + base);
    float4 b = *(const float4*)(g_part + 1 * (size_t)CSLAB + base);
    float4 d = *(const float4*)(g_part + 2 * (size_t)CSLAB + base);
    float4 e = *(const float4*)(g_part + 3 * (size_t)CSLAB + base);
    float4 bb = *(const float4*)(bo + col);
    float4 o;
    o.x = a.x + b.x + d.x + e.x + bb.x;
    o.y = a.y + b.y + d.y + e.y + bb.y;
    o.z = a.z + b.z + d.z + e.z + bb.z;
    o.w = a.w + b.w + d.w + e.w + bb.w;
    *(float4*)(out + base) = o;
}

// ---------------- attention: tensor-core, one block per (b,h) ----------------
#define SQ 0
#define SS 512
#define SSTR 1032
#define SL (SS + 8 * SSTR)
#define ST (SL + 16)
#define STG_STRIDE 68
#define STAGE_FLOATS (128 * STG_STRIDE)
#define SM_FLOATS (ST + 2 * STAGE_FLOATS)
#define SM_BYTES (SM_FLOATS * 4)

__device__ __forceinline__ void attn_issue(const float* __restrict__ cbase,
                                           const float* __restrict__ nbase,
                                           int c, int tid, uint32_t stg)
{
#pragma unroll
    for (int i = 0; i < 8; i++) {
        int j = tid + (i << 8);
        int sloc = j >> 4, d4 = j & 15;
        int s = c * 128 + sloc;
        const float* src = (s < CACHE_T) ? (cbase + (size_t)s * HEAD_DIM + (d4 << 2))
                                         : (nbase + (size_t)(s - CACHE_T) * D_MODEL + (d4 << 2));
        cp16(stg + (uint32_t)((sloc * STG_STRIDE + (d4 << 2)) * 4), src);
    }
}

__global__ __launch_bounds__(256) void attn_kernel(const float* __restrict__ cacheK,
                                                   const float* __restrict__ cacheV)
{
    extern __shared__ float sm[];
    const int bh = blockIdx.x;
    const int b = bh >> 5, h = bh & 31;
    const int tid = threadIdx.x, lane = tid & 31, wid = tid >> 5;
    const int lr = lane >> 2;
    const int lk = (lane & 3) * 2;

    const uint32_t stg_u32[2] = {
        (uint32_t)__cvta_generic_to_shared(sm + ST),
        (uint32_t)__cvta_generic_to_shared(sm + ST + STAGE_FLOATS)};

#pragma unroll
    for (int i = 0; i < 2; i++) {
        int j = tid + i * 256;
        int t = j >> 6, d = j & 63;
        sm[SQ + j] = 0.125f * g_q[(size_t)(b * TT + t) * D_MODEL + h * HEAD_DIM + d];
    }

    const float* cK = cacheK + (size_t)(b * N_HEADS + h) * CACHE_T * HEAD_DIM;
    const float* cV = cacheV + (size_t)(b * N_HEADS + h) * CACHE_T * HEAD_DIM;
    const float* nK = g_k + (size_t)(b * TT) * D_MODEL + h * HEAD_DIM;
    const float* nV = g_v + (size_t)(b * TT) * D_MODEL + h * HEAD_DIM;

    attn_issue(cK, nK, 0, tid, stg_u32[0]);
    CP_COMMIT;
    __syncthreads();

    uint32_t aqh[4][2], aql[4][2];
    const uint32_t zero = 0;
#pragma unroll
    for (int ks = 0; ks < 4; ks++) {
        float2 q0 = *(const float2*)&sm[SQ + lr * 64 + ks * 16 + lk];
        float2 q1 = *(const float2*)&sm[SQ + lr * 64 + ks * 16 + lk + 8];
        f2_hilo(q0, aqh[ks][0], aql[ks][0]);
        f2_hilo(q1, aqh[ks][1], aql[ks][1]);
    }

    // ---------- phase A: scores ----------
    for (int c = 0; c < 8; c++) {
        __syncthreads();
        if (c < 7) {
            attn_issue(cK, nK, c + 1, tid, stg_u32[(c + 1) & 1]);
            CP_COMMIT;
            asm volatile("cp.async.wait_group 1;\n" ::: "memory");
        } else {
            asm volatile("cp.async.wait_group 0;\n" ::: "memory");
        }
        __syncthreads();
        const float* stg = sm + ST + (c & 1) * STAGE_FLOATS;

        float cA[2][4];
#pragma unroll
        for (int nt = 0; nt < 2; nt++)
#pragma unroll
            for (int e = 0; e < 4; e++) cA[nt][e] = 0.0f;

#pragma unroll
        for (int ks = 0; ks < 4; ks++) {
            uint32_t kbh[2][2], kbl[2][2];
#pragma unroll
            for (int nt = 0; nt < 2; nt++) {
                int key = wid * 16 + nt * 8 + lr;
                float2 f0 = *(const float2*)&stg[key * STG_STRIDE + ks * 16 + lk];
                float2 f1 = *(const float2*)&stg[key * STG_STRIDE + ks * 16 + lk + 8];
                f2_hilo(f0, kbh[nt][0], kbl[nt][0]);
                f2_hilo(f1, kbh[nt][1], kbl[nt][1]);
            }
#pragma unroll
            for (int nt = 0; nt < 2; nt++)
                MMA_BF16(cA[nt], aqh[ks][0], zero, aqh[ks][1], zero, kbh[nt][0], kbh[nt][1]);
#pragma unroll
            for (int nt = 0; nt < 2; nt++)
                MMA_BF16(cA[nt], aqh[ks][0], zero, aqh[ks][1], zero, kbl[nt][0], kbl[nt][1]);
#pragma unroll
            for (int nt = 0; nt < 2; nt++)
                MMA_BF16(cA[nt], aql[ks][0], zero, aql[ks][1], zero, kbh[nt][0], kbh[nt][1]);
        }
#pragma unroll
        for (int nt = 0; nt < 2; nt++) {
            int col = c * 128 + wid * 16 + nt * 8 + lk;
            *(float2*)&sm[SS + lr * SSTR + col] = make_float2(cA[nt][0], cA[nt][1]);
        }
    }

    attn_issue(cV, nV, 0, tid, stg_u32[0]);
    CP_COMMIT;
    __syncthreads();

    // ---------- softmax ----------
    {
        const int qi = wid;
        if (qi < 8) {
            float m = -1e30f;
#pragma unroll
            for (int i = 0; i < 32; i++) m = fmaxf(m, sm[SS + qi * SSTR + lane + i * 32]);
#pragma unroll
            for (int off = 16; off >= 1; off >>= 1) m = fmaxf(m, __shfl_xor_sync(0xffffffffu, m, off));
            float ssum = 0.0f;
#pragma unroll
            for (int i = 0; i < 32; i++) {
                int idx = SS + qi * SSTR + lane + i * 32;
                float e = __expf(sm[idx] - m);
                sm[idx] = e;
                ssum += e;
            }
#pragma unroll
            for (int off = 16; off >= 1; off >>= 1) ssum += __shfl_xor_sync(0xffffffffu, ssum, off);
            if (lane == 0) sm[SL + qi] = 1.0f / ssum;
        }
    }
    __syncthreads();

    // ---------- phase B: out = P . V ----------
    float cav[8][4];
#pragma unroll
    for (int nt = 0; nt < 8; nt++)
#pragma unroll
        for (int e = 0; e < 4; e++) cav[nt][e] = 0.0f;

    for (int c = 0; c < 8; c++) {
        __syncthreads();
        if (c < 7) {
            attn_issue(cV, nV, c + 1, tid, stg_u32[(c + 1) & 1]);
            CP_COMMIT;
            asm volatile("cp.async.wait_group 1;\n" ::: "memory");
        } else {
            asm volatile("cp.async.wait_group 0;\n" ::: "memory");
        }
        __syncthreads();
        const float* stg = sm + ST + (c & 1) * STAGE_FLOATS;

        float2 p0 = *(const float2*)&sm[SS + lr * SSTR + c * 128 + wid * 16 + lk];
        float2 p1 = *(const float2*)&sm[SS + lr * SSTR + c * 128 + wid * 16 + lk + 8];
        uint32_t pah0, pal0, pah2, pal2;
        f2_hilo(p0, pah0, pal0);
        f2_hilo(p1, pah2, pal2);

        const int kb = wid * 16;
        uint32_t vbh[8][2], vbl[8][2];
#pragma unroll
        for (int nt = 0; nt < 8; nt++) {
            int n = nt * 8 + lr;
            float v0 = stg[(kb + lk + 0) * STG_STRIDE + n];
            float v1 = stg[(kb + lk + 1) * STG_STRIDE + n];
            float v8 = stg[(kb + lk + 8) * STG_STRIDE + n];
            float v9 = stg[(kb + lk + 9) * STG_STRIDE + n];
            f2_hilo(make_float2(v0, v1), vbh[nt][0], vbl[nt][0]);
            f2_hilo(make_float2(v8, v9), vbh[nt][1], vbl[nt][1]);
        }
#pragma unroll
        for (int nt = 0; nt < 8; nt++)
            MMA_BF16(cav[nt], pah0, zero, pah2, zero, vbh[nt][0], vbh[nt][1]);
#pragma unroll
        for (int nt = 0; nt < 8; nt++)
            MMA_BF16(cav[nt], pah0, zero, pah2, zero, vbl[nt][0], vbl[nt][1]);
#pragma unroll
        for (int nt = 0; nt < 8; nt++)
            MMA_BF16(cav[nt], pal0, zero, pal2, zero, vbh[nt][0], vbh[nt][1]);
    }
    __syncthreads();

#pragma unroll
    for (int nt = 0; nt < 8; nt++)
        *(float2*)&sm[ST + wid * 544 + lr * STG_STRIDE + nt * 8 + lk] =
            make_float2(cav[nt][0], cav[nt][1]);
    __syncthreads();
#pragma unroll
    for (int r = 0; r < 2; r++) {
        int o = tid + r * 256;
        int qi = o >> 6, d = o & 63;
        float s = 0.0f;
#pragma unroll
        for (int gg = 0; gg < 8; gg++) s += sm[ST + gg * 544 + qi * STG_STRIDE + d];
        g_ao[(size_t)(b * TT + qi) * D_MODEL + h * HEAD_DIM + d] = s * sm[SL + qi];
    }
}

// ---------------- launch ----------------
extern "C" void kernel_launch(void* const* d_in, const int* in_sizes, int n_in,
                              void* d_out, int out_size)
{
    const float* x  = (const float*)d_in[0];
    const float* cK = (const float*)d_in[1];
    const float* cV = (const float*)d_in[2];
    const float* Wq = (const float*)d_in[3];
    const float* bq = (const float*)d_in[4];
    const float* Wk = (const float*)d_in[5];
    const float* bk = (const float*)d_in[6];
    const float* Wv = (const float*)d_in[7];
    const float* bv = (const float*)d_in[8];
    const float* Wo = (const float*)d_in[9];
    const float* bo = (const float*)d_in[10];
    float* out = (float*)d_out;

    cudaFuncSetAttribute((const void*)attn_kernel,
                         cudaFuncAttributeMaxDynamicSharedMemorySize, SM_BYTES);
    cudaFuncSetAttribute((const void*)gemm_bf16,
                         cudaFuncAttributeMaxDynamicSharedMemorySize, GEMM_SMEM);
    (void)cudaGetLastError();

    // pre-convert W(q,k,v,o) + x to bf16 hi/lo planes
    conv_split<<<dim3(192, 5), 256>>>(Wq, Wk, Wv, Wo, x);

    // QKV: full-K, no split, bias in epilogue (96 blocks)
    gemm_bf16<<<dim3(16, 2, 3), 512, GEMM_SMEM>>>(0, bq, bk, bv);

    attn_kernel<<<N_HEADS * 32, 256, SM_BYTES>>>(cK, cV);

    // O: convert attention output, split-K 4 (128 blocks), reduce
    conv_ao<<<64, 256>>>();
    gemm_bf16<<<dim3(16, 2, 4), 512, GEMM_SMEM>>>(1, bq, bk, bv);
    reduce_o<<<512, 256>>>(bo, out);
}

// round 16
// speedup vs baseline: 1.4660x; 1.4660x over previous
#include <cuda_runtime.h>
#include <cuda_bf16.h>
#include <cuda_fp16.h>
#include <cstdint>

#define D_MODEL 2048
#define N_HEADS 32
#define HEAD_DIM 64
#define TT 8
#define MROWS 256
#define CACHE_T 1016
#define SEQ 1024

// ---------------- scratch ----------------
__device__ float g_q[MROWS * D_MODEL];
__device__ float g_k[MROWS * D_MODEL];
__device__ float g_v[MROWS * D_MODEL];
__device__ float g_ao[MROWS * D_MODEL];
__device__ float g_part[9 * MROWS * D_MODEL];

#define CSLAB (MROWS * D_MODEL)

// ---------------- common helpers ----------------
#define MMA_BF16(d, a0, a1, a2, a3, b0, b1)                                      \
    asm volatile("mma.sync.aligned.m16n8k16.row.col.f32.bf16.bf16.f32 "          \
                 "{%0,%1,%2,%3}, {%4,%5,%6,%7}, {%8,%9}, {%0,%1,%2,%3};\n"       \
                 : "+f"(d[0]), "+f"(d[1]), "+f"(d[2]), "+f"(d[3])                \
                 : "r"(a0), "r"(a1), "r"(a2), "r"(a3), "r"(b0), "r"(b1))

#define MMA_F16(d, a0, a1, a2, a3, b0, b1)                                       \
    asm volatile("mma.sync.aligned.m16n8k16.row.col.f32.f16.f16.f32 "            \
                 "{%0,%1,%2,%3}, {%4,%5,%6,%7}, {%8,%9}, {%0,%1,%2,%3};\n"       \
                 : "+f"(d[0]), "+f"(d[1]), "+f"(d[2]), "+f"(d[3])                \
                 : "r"(a0), "r"(a1), "r"(a2), "r"(a3), "r"(b0), "r"(b1))

#define LDSM4(r0, r1, r2, r3, addr)                                              \
    asm volatile("ldmatrix.sync.aligned.m8n8.x4.shared.b16 {%0,%1,%2,%3}, [%4];" \
                 : "=r"(r0), "=r"(r1), "=r"(r2), "=r"(r3) : "r"(addr))

__device__ __forceinline__ void f2_hilo(float2 f, uint32_t& hi, uint32_t& lo)
{
    __nv_bfloat162 h = __floats2bfloat162_rn(f.x, f.y);
    float2 hf = __bfloat1622float2(h);
    __nv_bfloat162 l = __floats2bfloat162_rn(f.x - hf.x, f.y - hf.y);
    hi = *reinterpret_cast<uint32_t*>(&h);
    lo = *reinterpret_cast<uint32_t*>(&l);
}

// fp16 split store: A = hi + lo (hi/lo planes), one STS.64 each
__device__ __forceinline__ void split_store64_h(__half* hi, __half* lo, float4 v)
{
    __half2 h01 = __floats2half2_rn(v.x, v.y);
    __half2 h23 = __floats2half2_rn(v.z, v.w);
    float2 f01 = __half22float2(h01);
    float2 f23 = __half22float2(h23);
    __half2 l01 = __floats2half2_rn(v.x - f01.x, v.y - f01.y);
    __half2 l23 = __floats2half2_rn(v.z - f23.x, v.w - f23.y);
    uint2 h, l;
    h.x = *reinterpret_cast<uint32_t*>(&h01);
    h.y = *reinterpret_cast<uint32_t*>(&h23);
    l.x = *reinterpret_cast<uint32_t*>(&l01);
    l.y = *reinterpret_cast<uint32_t*>(&l23);
    *reinterpret_cast<uint2*>(hi) = h;
    *reinterpret_cast<uint2*>(lo) = l;
}

// fp16 single-round store
__device__ __forceinline__ void store64_h(__half* dst, float4 v)
{
    __half2 h01 = __floats2half2_rn(v.x, v.y);
    __half2 h23 = __floats2half2_rn(v.z, v.w);
    uint2 h;
    h.x = *reinterpret_cast<uint32_t*>(&h01);
    h.y = *reinterpret_cast<uint32_t*>(&h23);
    *reinterpret_cast<uint2*>(dst) = h;
}

// ---------------- GEMM (fp16 2-term: Ah*B + Al*B), GBK=64, 1 sync/chunk ----------------
#define GBK 64
#define KST 72                      // 144B rows: LDSM + STS conflict-free
#define ATILE (128 * KST)           // fp16 elems per plane
#define NKT 32                      // 2048 / 64
#define GEMM_SMEM (6 * ATILE * 2)   // 110592 bytes: A-hi,A-lo,B x 2 bufs

template <int SPLITS>
__global__ __launch_bounds__(512) void gemm_kernel(
    const float* __restrict__ Aext,
    const float* __restrict__ W0, const float* __restrict__ W1, const float* __restrict__ W2,
    int mode)
{
    extern __shared__ __half gsm[];
    // A planes: (buf*2 + {0=hi,1=lo})*ATILE ; B plane: (4 + buf)*ATILE

    const int z = blockIdx.z;
    const int wz = z / SPLITS, kslice = z % SPLITS;
    const float* A = (mode == 0) ? Aext : g_ao;
    const float* W = (mode == 0) ? ((wz == 0) ? W0 : (wz == 1) ? W1 : W2) : W0;
    float* C = g_part + (size_t)z * CSLAB;

    const int kt0 = (NKT * kslice) / SPLITS;
    const int kt1 = (NKT * (kslice + 1)) / SPLITS;
    const int NT = kt1 - kt0;

    const int m0 = blockIdx.y * 128;
    const int n0 = blockIdx.x * 128;
    const int tid = threadIdx.x;
    const int lane = tid & 31, wid = tid >> 5;
    const int wm = (wid & 3) * 32;
    const int wn = (wid >> 2) * 32;

    float c[2][4][4];
#pragma unroll
    for (int i = 0; i < 2; i++)
#pragma unroll
        for (int j = 0; j < 4; j++)
#pragma unroll
            for (int e = 0; e < 4; e++) c[i][j][e] = 0.0f;

    const uint32_t smb = (uint32_t)__cvta_generic_to_shared(gsm);
    const int arow = wm + (lane & 15);
    const int akof = (lane >> 4) * 8;
    const int brow_base = wn + ((lane >> 4) * 8) + (lane & 7);
    const int bkof = ((lane >> 3) & 1) * 8;

    float4 pa[4], pb[4];

    auto ldg_tile = [&](int kt) {
        int k0 = kt * GBK;
#pragma unroll
        for (int p = 0; p < 4; p++) {
            int idx = tid + p * 512;
            int r = idx >> 4, c4 = (idx & 15) * 4;
            pa[p] = *(const float4*)(A + (size_t)(m0 + r) * D_MODEL + k0 + c4);
            pb[p] = *(const float4*)(W + (size_t)(n0 + r) * D_MODEL + k0 + c4);
        }
    };
    auto store_tile = [&](int buf) {
        __half* ah = gsm + (buf * 2 + 0) * ATILE;
        __half* al = gsm + (buf * 2 + 1) * ATILE;
        __half* bs = gsm + (4 + buf) * ATILE;
#pragma unroll
        for (int p = 0; p < 4; p++) {
            int idx = tid + p * 512;
            int r = idx >> 4, c4 = (idx & 15) * 4;
            split_store64_h(&ah[r * KST + c4], &al[r * KST + c4], pa[p]);
            store64_h(&bs[r * KST + c4], pb[p]);
        }
    };

    ldg_tile(kt0);
    store_tile(0);
    if (NT > 1) ldg_tile(kt0 + 1);

    for (int it = 0; it < NT; it++) {
        __syncthreads();
        if (it + 1 < NT) store_tile((it + 1) & 1);
        if (it + 2 < NT) ldg_tile(kt0 + it + 2);

        const int buf = it & 1;
        const uint32_t a_h = smb + (uint32_t)((buf * 2 + 0) * ATILE) * 2;
        const uint32_t a_l = smb + (uint32_t)((buf * 2 + 1) * ATILE) * 2;
        const uint32_t b_s = smb + (uint32_t)((4 + buf) * ATILE) * 2;

#pragma unroll
        for (int ks = 0; ks < GBK; ks += 16) {
            uint32_t ah[2][4], al[2][4], bb[4][2];
#pragma unroll
            for (int i = 0; i < 2; i++) {
                uint32_t off = (uint32_t)(((arow + i * 16) * KST + ks + akof) * 2);
                LDSM4(ah[i][0], ah[i][1], ah[i][2], ah[i][3], a_h + off);
                LDSM4(al[i][0], al[i][1], al[i][2], al[i][3], a_l + off);
            }
#pragma unroll
            for (int jp = 0; jp < 2; jp++) {
                uint32_t off = (uint32_t)(((brow_base + jp * 16) * KST + ks + bkof) * 2);
                LDSM4(bb[jp * 2][0], bb[jp * 2][1], bb[jp * 2 + 1][0], bb[jp * 2 + 1][1], b_s + off);
            }
#pragma unroll
            for (int i = 0; i < 2; i++)
#pragma unroll
                for (int j = 0; j < 4; j++)
                    MMA_F16(c[i][j], ah[i][0], ah[i][1], ah[i][2], ah[i][3], bb[j][0], bb[j][1]);
#pragma unroll
            for (int i = 0; i < 2; i++)
#pragma unroll
                for (int j = 0; j < 4; j++)
                    MMA_F16(c[i][j], al[i][0], al[i][1], al[i][2], al[i][3], bb[j][0], bb[j][1]);
        }
    }

#pragma unroll
    for (int i = 0; i < 2; i++)
#pragma unroll
        for (int j = 0; j < 4; j++) {
            int row = m0 + wm + i * 16 + (lane >> 2);
            int col = n0 + wn + j * 8 + (lane & 3) * 2;
            C[(size_t)row * D_MODEL + col]           = c[i][j][0];
            C[(size_t)row * D_MODEL + col + 1]       = c[i][j][1];
            C[(size_t)(row + 8) * D_MODEL + col]     = c[i][j][2];
            C[(size_t)(row + 8) * D_MODEL + col + 1] = c[i][j][3];
        }
}

// ---------------- split-K reduce ----------------
__global__ __launch_bounds__(256) void reduce_qkv(
    const float* __restrict__ bq, const float* __restrict__ bk, const float* __restrict__ bv)
{
    const int z = blockIdx.y;
    float* out = (z == 0) ? g_q : (z == 1) ? g_k : g_v;
    const float* bias = (z == 0) ? bq : (z == 1) ? bk : bv;
    size_t base = ((size_t)blockIdx.x * 256 + threadIdx.x) * 4;
    int col = (int)(base & (D_MODEL - 1));
    float4 a = *(const float4*)(g_part + (size_t)(z * 3 + 0) * CSLAB + base);
    float4 b = *(const float4*)(g_part + (size_t)(z * 3 + 1) * CSLAB + base);
    float4 d = *(const float4*)(g_part + (size_t)(z * 3 + 2) * CSLAB + base);
    float4 bb = *(const float4*)(bias + col);
    float4 o;
    o.x = a.x + b.x + d.x + bb.x;
    o.y = a.y + b.y + d.y + bb.y;
    o.z = a.z + b.z + d.z + bb.z;
    o.w = a.w + b.w + d.w + bb.w;
    *(float4*)(out + base) = o;
}

__global__ __launch_bounds__(256) void reduce_o(const float* __restrict__ bo, float* __restrict__ out)
{
    size_t base = ((size_t)blockIdx.x * 256 + threadIdx.x) * 4;
    int col = (int)(base & (D_MODEL - 1));
    float4 a = *(const float4*)(g_part + 0 * (size_t)CSLAB + base);
    float4 b = *(const float4*)(g_part + 1 * (size_t)CSLAB + base);
    float4 d = *(const float4*)(g_part + 2 * (size_t)CSLAB + base);
    float4 e = *(const float4*)(g_part + 3 * (size_t)CSLAB + base);
    float4 bb = *(const float4*)(bo + col);
    float4 o;
    o.x = a.x + b.x + d.x + e.x + bb.x;
    o.y = a.y + b.y + d.y + e.y + bb.y;
    o.z = a.z + b.z + d.z + e.z + bb.z;
    o.w = a.w + b.w + d.w + e.w + bb.w;
    *(float4*)(out + base) = o;
}

// ---------------- attention: tensor-core (bf16 3-term), one block per (b,h) ----------------
#define SQ 0
#define SS 512
#define SSTR 1032
#define SL (SS + 8 * SSTR)
#define ST (SL + 16)
#define STG_STRIDE 68
#define STAGE_FLOATS (128 * STG_STRIDE)
#define SM_FLOATS (ST + 2 * STAGE_FLOATS)
#define SM_BYTES (SM_FLOATS * 4)

#define CP_COMMIT asm volatile("cp.async.commit_group;\n" ::: "memory")

__device__ __forceinline__ void cp16(uint32_t dst, const float* src)
{
    asm volatile("cp.async.cg.shared.global [%0], [%1], 16;\n" ::"r"(dst), "l"(src));
}

__device__ __forceinline__ void attn_issue(const float* __restrict__ cbase,
                                           const float* __restrict__ nbase,
                                           int c, int tid, uint32_t stg)
{
#pragma unroll
    for (int i = 0; i < 8; i++) {
        int j = tid + (i << 8);
        int sloc = j >> 4, d4 = j & 15;
        int s = c * 128 + sloc;
        const float* src = (s < CACHE_T) ? (cbase + (size_t)s * HEAD_DIM + (d4 << 2))
                                         : (nbase + (size_t)(s - CACHE_T) * D_MODEL + (d4 << 2));
        cp16(stg + (uint32_t)((sloc * STG_STRIDE + (d4 << 2)) * 4), src);
    }
}

__global__ __launch_bounds__(256) void attn_kernel(const float* __restrict__ cacheK,
                                                   const float* __restrict__ cacheV)
{
    extern __shared__ float sm[];
    const int bh = blockIdx.x;
    const int b = bh >> 5, h = bh & 31;
    const int tid = threadIdx.x, lane = tid & 31, wid = tid >> 5;
    const int lr = lane >> 2;
    const int lk = (lane & 3) * 2;

    const uint32_t stg_u32[2] = {
        (uint32_t)__cvta_generic_to_shared(sm + ST),
        (uint32_t)__cvta_generic_to_shared(sm + ST + STAGE_FLOATS)};

#pragma unroll
    for (int i = 0; i < 2; i++) {
        int j = tid + i * 256;
        int t = j >> 6, d = j & 63;
        sm[SQ + j] = 0.125f * g_q[(size_t)(b * TT + t) * D_MODEL + h * HEAD_DIM + d];
    }

    const float* cK = cacheK + (size_t)(b * N_HEADS + h) * CACHE_T * HEAD_DIM;
    const float* cV = cacheV + (size_t)(b * N_HEADS + h) * CACHE_T * HEAD_DIM;
    const float* nK = g_k + (size_t)(b * TT) * D_MODEL + h * HEAD_DIM;
    const float* nV = g_v + (size_t)(b * TT) * D_MODEL + h * HEAD_DIM;

    attn_issue(cK, nK, 0, tid, stg_u32[0]);
    CP_COMMIT;
    __syncthreads();

    uint32_t aqh[4][2], aql[4][2];
    const uint32_t zero = 0;
#pragma unroll
    for (int ks = 0; ks < 4; ks++) {
        float2 q0 = *(const float2*)&sm[SQ + lr * 64 + ks * 16 + lk];
        float2 q1 = *(const float2*)&sm[SQ + lr * 64 + ks * 16 + lk + 8];
        f2_hilo(q0, aqh[ks][0], aql[ks][0]);
        f2_hilo(q1, aqh[ks][1], aql[ks][1]);
    }

    // ---------- phase A: scores ----------
    for (int c = 0; c < 8; c++) {
        __syncthreads();
        if (c < 7) {
            attn_issue(cK, nK, c + 1, tid, stg_u32[(c + 1) & 1]);
            CP_COMMIT;
            asm volatile("cp.async.wait_group 1;\n" ::: "memory");
        } else {
            asm volatile("cp.async.wait_group 0;\n" ::: "memory");
        }
        __syncthreads();
        const float* stg = sm + ST + (c & 1) * STAGE_FLOATS;

        float cA[2][4];
#pragma unroll
        for (int nt = 0; nt < 2; nt++)
#pragma unroll
            for (int e = 0; e < 4; e++) cA[nt][e] = 0.0f;

#pragma unroll
        for (int ks = 0; ks < 4; ks++) {
            uint32_t kbh[2][2], kbl[2][2];
#pragma unroll
            for (int nt = 0; nt < 2; nt++) {
                int key = wid * 16 + nt * 8 + lr;
                float2 f0 = *(const float2*)&stg[key * STG_STRIDE + ks * 16 + lk];
                float2 f1 = *(const float2*)&stg[key * STG_STRIDE + ks * 16 + lk + 8];
                f2_hilo(f0, kbh[nt][0], kbl[nt][0]);
                f2_hilo(f1, kbh[nt][1], kbl[nt][1]);
            }
#pragma unroll
            for (int nt = 0; nt < 2; nt++)
                MMA_BF16(cA[nt], aqh[ks][0], zero, aqh[ks][1], zero, kbh[nt][0], kbh[nt][1]);
#pragma unroll
            for (int nt = 0; nt < 2; nt++)
                MMA_BF16(cA[nt], aqh[ks][0], zero, aqh[ks][1], zero, kbl[nt][0], kbl[nt][1]);
#pragma unroll
            for (int nt = 0; nt < 2; nt++)
                MMA_BF16(cA[nt], aql[ks][0], zero, aql[ks][1], zero, kbh[nt][0], kbh[nt][1]);
        }
#pragma unroll
        for (int nt = 0; nt < 2; nt++) {
            int col = c * 128 + wid * 16 + nt * 8 + lk;
            *(float2*)&sm[SS + lr * SSTR + col] = make_float2(cA[nt][0], cA[nt][1]);
        }
    }

    attn_issue(cV, nV, 0, tid, stg_u32[0]);
    CP_COMMIT;
    __syncthreads();

    // ---------- softmax ----------
    {
        const int qi = wid;
        if (qi < 8) {
            float m = -1e30f;
#pragma unroll
            for (int i = 0; i < 32; i++) m = fmaxf(m, sm[SS + qi * SSTR + lane + i * 32]);
#pragma unroll
            for (int off = 16; off >= 1; off >>= 1) m = fmaxf(m, __shfl_xor_sync(0xffffffffu, m, off));
            float ssum = 0.0f;
#pragma unroll
            for (int i = 0; i < 32; i++) {
                int idx = SS + qi * SSTR + lane + i * 32;
                float e = __expf(sm[idx] - m);
                sm[idx] = e;
                ssum += e;
            }
#pragma unroll
            for (int off = 16; off >= 1; off >>= 1) ssum += __shfl_xor_sync(0xffffffffu, ssum, off);
            if (lane == 0) sm[SL + qi] = 1.0f / ssum;
        }
    }
    __syncthreads();

    // ---------- phase B: out = P . V ----------
    float cav[8][4];
#pragma unroll
    for (int nt = 0; nt < 8; nt++)
#pragma unroll
        for (int e = 0; e < 4; e++) cav[nt][e] = 0.0f;

    for (int c = 0; c < 8; c++) {
        __syncthreads();
        if (c < 7) {
            attn_issue(cV, nV, c + 1, tid, stg_u32[(c + 1) & 1]);
            CP_COMMIT;
            asm volatile("cp.async.wait_group 1;\n" ::: "memory");
        } else {
            asm volatile("cp.async.wait_group 0;\n" ::: "memory");
        }
        __syncthreads();
        const float* stg = sm + ST + (c & 1) * STAGE_FLOATS;

        float2 p0 = *(const float2*)&sm[SS + lr * SSTR + c * 128 + wid * 16 + lk];
        float2 p1 = *(const float2*)&sm[SS + lr * SSTR + c * 128 + wid * 16 + lk + 8];
        uint32_t pah0, pal0, pah2, pal2;
        f2_hilo(p0, pah0, pal0);
        f2_hilo(p1, pah2, pal2);

        const int kb = wid * 16;
        uint32_t vbh[8][2], vbl[8][2];
#pragma unroll
        for (int nt = 0; nt < 8; nt++) {
            int n = nt * 8 + lr;
            float v0 = stg[(kb + lk + 0) * STG_STRIDE + n];
            float v1 = stg[(kb + lk + 1) * STG_STRIDE + n];
            float v8 = stg[(kb + lk + 8) * STG_STRIDE + n];
            float v9 = stg[(kb + lk + 9) * STG_STRIDE + n];
            f2_hilo(make_float2(v0, v1), vbh[nt][0], vbl[nt][0]);
            f2_hilo(make_float2(v8, v9), vbh[nt][1], vbl[nt][1]);
        }
#pragma unroll
        for (int nt = 0; nt < 8; nt++)
            MMA_BF16(cav[nt], pah0, zero, pah2, zero, vbh[nt][0], vbh[nt][1]);
#pragma unroll
        for (int nt = 0; nt < 8; nt++)
            MMA_BF16(cav[nt], pah0, zero, pah2, zero, vbl[nt][0], vbl[nt][1]);
#pragma unroll
        for (int nt = 0; nt < 8; nt++)
            MMA_BF16(cav[nt], pal0, zero, pal2, zero, vbh[nt][0], vbh[nt][1]);
    }
    __syncthreads();

#pragma unroll
    for (int nt = 0; nt < 8; nt++)
        *(float2*)&sm[ST + wid * 544 + lr * STG_STRIDE + nt * 8 + lk] =
            make_float2(cav[nt][0], cav[nt][1]);
    __syncthreads();
#pragma unroll
    for (int r = 0; r < 2; r++) {
        int o = tid + r * 256;
        int qi = o >> 6, d = o & 63;
        float s = 0.0f;
#pragma unroll
        for (int gg = 0; gg < 8; gg++) s += sm[ST + gg * 544 + qi * STG_STRIDE + d];
        g_ao[(size_t)(b * TT + qi) * D_MODEL + h * HEAD_DIM + d] = s * sm[SL + qi];
    }
}

// ---------------- launch ----------------
extern "C" void kernel_launch(void* const* d_in, const int* in_sizes, int n_in,
                              void* d_out, int out_size)
{
    const float* x  = (const float*)d_in[0];
    const float* cK = (const float*)d_in[1];
    const float* cV = (const float*)d_in[2];
    const float* Wq = (const float*)d_in[3];
    const float* bq = (const float*)d_in[4];
    const float* Wk = (const float*)d_in[5];
    const float* bk = (const float*)d_in[6];
    const float* Wv = (const float*)d_in[7];
    const float* bv = (const float*)d_in[8];
    const float* Wo = (const float*)d_in[9];
    const float* bo = (const float*)d_in[10];
    float* out = (float*)d_out;

    cudaFuncSetAttribute((const void*)attn_kernel,
                         cudaFuncAttributeMaxDynamicSharedMemorySize, SM_BYTES);
    cudaFuncSetAttribute((const void*)gemm_kernel<3>,
                         cudaFuncAttributeMaxDynamicSharedMemorySize, GEMM_SMEM);
    cudaFuncSetAttribute((const void*)gemm_kernel<4>,
                         cudaFuncAttributeMaxDynamicSharedMemorySize, GEMM_SMEM);
    (void)cudaGetLastError();

    gemm_kernel<3><<<dim3(16, 2, 9), 512, GEMM_SMEM>>>(x, Wq, Wk, Wv, 0);
    reduce_qkv<<<dim3(512, 3), 256>>>(bq, bk, bv);

    attn_kernel<<<N_HEADS * 32, 256, SM_BYTES>>>(cK, cV);

    gemm_kernel<4><<<dim3(16, 2, 4), 512, GEMM_SMEM>>>(x, Wo, Wo, Wo, 1);
    reduce_o<<<512, 256>>>(bo, out);
}

// round 17
// speedup vs baseline: 1.4696x; 1.0024x over previous
#include <cuda_runtime.h>
#include <cuda_bf16.h>
#include <cuda_fp16.h>
#include <cstdint>

#define D_MODEL 2048
#define N_HEADS 32
#define HEAD_DIM 64
#define TT 8
#define MROWS 256
#define CACHE_T 1016
#define SEQ 1024

// ---------------- scratch ----------------
__device__ float g_q[MROWS * D_MODEL];
__device__ float g_k[MROWS * D_MODEL];
__device__ float g_v[MROWS * D_MODEL];
__device__ float g_ao[MROWS * D_MODEL];
__device__ float g_part[9 * MROWS * D_MODEL];

#define CSLAB (MROWS * D_MODEL)

// ---------------- common helpers ----------------
#define MMA_F16(d, a0, a1, a2, a3, b0, b1)                                       \
    asm volatile("mma.sync.aligned.m16n8k16.row.col.f32.f16.f16.f32 "            \
                 "{%0,%1,%2,%3}, {%4,%5,%6,%7}, {%8,%9}, {%0,%1,%2,%3};\n"       \
                 : "+f"(d[0]), "+f"(d[1]), "+f"(d[2]), "+f"(d[3])                \
                 : "r"(a0), "r"(a1), "r"(a2), "r"(a3), "r"(b0), "r"(b1))

#define LDSM4(r0, r1, r2, r3, addr)                                              \
    asm volatile("ldmatrix.sync.aligned.m8n8.x4.shared.b16 {%0,%1,%2,%3}, [%4];" \
                 : "=r"(r0), "=r"(r1), "=r"(r2), "=r"(r3) : "r"(addr))

// fp16 hi/lo split of a float2 pair
__device__ __forceinline__ void f2_hilo_h(float2 f, uint32_t& hi, uint32_t& lo)
{
    __half2 h = __floats2half2_rn(f.x, f.y);
    float2 hf = __half22float2(h);
    __half2 l = __floats2half2_rn(f.x - hf.x, f.y - hf.y);
    hi = *reinterpret_cast<uint32_t*>(&h);
    lo = *reinterpret_cast<uint32_t*>(&l);
}

// fp16 single-round of a float2 pair
__device__ __forceinline__ uint32_t f2_h(float2 f)
{
    __half2 h = __floats2half2_rn(f.x, f.y);
    return *reinterpret_cast<uint32_t*>(&h);
}

// fp16 split store: A = hi + lo (hi/lo planes), one STS.64 each
__device__ __forceinline__ void split_store64_h(__half* hi, __half* lo, float4 v)
{
    __half2 h01 = __floats2half2_rn(v.x, v.y);
    __half2 h23 = __floats2half2_rn(v.z, v.w);
    float2 f01 = __half22float2(h01);
    float2 f23 = __half22float2(h23);
    __half2 l01 = __floats2half2_rn(v.x - f01.x, v.y - f01.y);
    __half2 l23 = __floats2half2_rn(v.z - f23.x, v.w - f23.y);
    uint2 h, l;
    h.x = *reinterpret_cast<uint32_t*>(&h01);
    h.y = *reinterpret_cast<uint32_t*>(&h23);
    l.x = *reinterpret_cast<uint32_t*>(&l01);
    l.y = *reinterpret_cast<uint32_t*>(&l23);
    *reinterpret_cast<uint2*>(hi) = h;
    *reinterpret_cast<uint2*>(lo) = l;
}

// fp16 single-round store
__device__ __forceinline__ void store64_h(__half* dst, float4 v)
{
    __half2 h01 = __floats2half2_rn(v.x, v.y);
    __half2 h23 = __floats2half2_rn(v.z, v.w);
    uint2 h;
    h.x = *reinterpret_cast<uint32_t*>(&h01);
    h.y = *reinterpret_cast<uint32_t*>(&h23);
    *reinterpret_cast<uint2*>(dst) = h;
}

// ---------------- GEMM (fp16 2-term: Ah*B + Al*B), GBK=64, 1 sync/chunk ----------------
#define GBK 64
#define KST 72
#define ATILE (128 * KST)
#define NKT 32
#define GEMM_SMEM (6 * ATILE * 2)   // 110592 bytes

template <int SPLITS>
__global__ __launch_bounds__(512) void gemm_kernel(
    const float* __restrict__ Aext,
    const float* __restrict__ W0, const float* __restrict__ W1, const float* __restrict__ W2,
    int mode)
{
    extern __shared__ __half gsm[];

    const int z = blockIdx.z;
    const int wz = z / SPLITS, kslice = z % SPLITS;
    const float* A = (mode == 0) ? Aext : g_ao;
    const float* W = (mode == 0) ? ((wz == 0) ? W0 : (wz == 1) ? W1 : W2) : W0;
    float* C = g_part + (size_t)z * CSLAB;

    const int kt0 = (NKT * kslice) / SPLITS;
    const int kt1 = (NKT * (kslice + 1)) / SPLITS;
    const int NT = kt1 - kt0;

    const int m0 = blockIdx.y * 128;
    const int n0 = blockIdx.x * 128;
    const int tid = threadIdx.x;
    const int lane = tid & 31, wid = tid >> 5;
    const int wm = (wid & 3) * 32;
    const int wn = (wid >> 2) * 32;

    float c[2][4][4];
#pragma unroll
    for (int i = 0; i < 2; i++)
#pragma unroll
        for (int j = 0; j < 4; j++)
#pragma unroll
            for (int e = 0; e < 4; e++) c[i][j][e] = 0.0f;

    const uint32_t smb = (uint32_t)__cvta_generic_to_shared(gsm);
    const int arow = wm + (lane & 15);
    const int akof = (lane >> 4) * 8;
    const int brow_base = wn + ((lane >> 4) * 8) + (lane & 7);
    const int bkof = ((lane >> 3) & 1) * 8;

    float4 pa[4], pb[4];

    auto ldg_tile = [&](int kt) {
        int k0 = kt * GBK;
#pragma unroll
        for (int p = 0; p < 4; p++) {
            int idx = tid + p * 512;
            int r = idx >> 4, c4 = (idx & 15) * 4;
            pa[p] = *(const float4*)(A + (size_t)(m0 + r) * D_MODEL + k0 + c4);
            pb[p] = *(const float4*)(W + (size_t)(n0 + r) * D_MODEL + k0 + c4);
        }
    };
    auto store_tile = [&](int buf) {
        __half* ah = gsm + (buf * 2 + 0) * ATILE;
        __half* al = gsm + (buf * 2 + 1) * ATILE;
        __half* bs = gsm + (4 + buf) * ATILE;
#pragma unroll
        for (int p = 0; p < 4; p++) {
            int idx = tid + p * 512;
            int r = idx >> 4, c4 = (idx & 15) * 4;
            split_store64_h(&ah[r * KST + c4], &al[r * KST + c4], pa[p]);
            store64_h(&bs[r * KST + c4], pb[p]);
        }
    };

    ldg_tile(kt0);
    store_tile(0);
    if (NT > 1) ldg_tile(kt0 + 1);

    for (int it = 0; it < NT; it++) {
        __syncthreads();
        if (it + 1 < NT) store_tile((it + 1) & 1);
        if (it + 2 < NT) ldg_tile(kt0 + it + 2);

        const int buf = it & 1;
        const uint32_t a_h = smb + (uint32_t)((buf * 2 + 0) * ATILE) * 2;
        const uint32_t a_l = smb + (uint32_t)((buf * 2 + 1) * ATILE) * 2;
        const uint32_t b_s = smb + (uint32_t)((4 + buf) * ATILE) * 2;

#pragma unroll
        for (int ks = 0; ks < GBK; ks += 16) {
            uint32_t ah[2][4], al[2][4], bb[4][2];
#pragma unroll
            for (int i = 0; i < 2; i++) {
                uint32_t off = (uint32_t)(((arow + i * 16) * KST + ks + akof) * 2);
                LDSM4(ah[i][0], ah[i][1], ah[i][2], ah[i][3], a_h + off);
                LDSM4(al[i][0], al[i][1], al[i][2], al[i][3], a_l + off);
            }
#pragma unroll
            for (int jp = 0; jp < 2; jp++) {
                uint32_t off = (uint32_t)(((brow_base + jp * 16) * KST + ks + bkof) * 2);
                LDSM4(bb[jp * 2][0], bb[jp * 2][1], bb[jp * 2 + 1][0], bb[jp * 2 + 1][1], b_s + off);
            }
#pragma unroll
            for (int i = 0; i < 2; i++)
#pragma unroll
                for (int j = 0; j < 4; j++)
                    MMA_F16(c[i][j], ah[i][0], ah[i][1], ah[i][2], ah[i][3], bb[j][0], bb[j][1]);
#pragma unroll
            for (int i = 0; i < 2; i++)
#pragma unroll
                for (int j = 0; j < 4; j++)
                    MMA_F16(c[i][j], al[i][0], al[i][1], al[i][2], al[i][3], bb[j][0], bb[j][1]);
        }
    }

#pragma unroll
    for (int i = 0; i < 2; i++)
#pragma unroll
        for (int j = 0; j < 4; j++) {
            int row = m0 + wm + i * 16 + (lane >> 2);
            int col = n0 + wn + j * 8 + (lane & 3) * 2;
            C[(size_t)row * D_MODEL + col]           = c[i][j][0];
            C[(size_t)row * D_MODEL + col + 1]       = c[i][j][1];
            C[(size_t)(row + 8) * D_MODEL + col]     = c[i][j][2];
            C[(size_t)(row + 8) * D_MODEL + col + 1] = c[i][j][3];
        }
}

// ---------------- split-K reduce ----------------
__global__ __launch_bounds__(256) void reduce_qkv(
    const float* __restrict__ bq, const float* __restrict__ bk, const float* __restrict__ bv)
{
    const int z = blockIdx.y;
    float* out = (z == 0) ? g_q : (z == 1) ? g_k : g_v;
    const float* bias = (z == 0) ? bq : (z == 1) ? bk : bv;
    size_t base = ((size_t)blockIdx.x * 256 + threadIdx.x) * 4;
    int col = (int)(base & (D_MODEL - 1));
    float4 a = *(const float4*)(g_part + (size_t)(z * 3 + 0) * CSLAB + base);
    float4 b = *(const float4*)(g_part + (size_t)(z * 3 + 1) * CSLAB + base);
    float4 d = *(const float4*)(g_part + (size_t)(z * 3 + 2) * CSLAB + base);
    float4 bb = *(const float4*)(bias + col);
    float4 o;
    o.x = a.x + b.x + d.x + bb.x;
    o.y = a.y + b.y + d.y + bb.y;
    o.z = a.z + b.z + d.z + bb.z;
    o.w = a.w + b.w + d.w + bb.w;
    *(float4*)(out + base) = o;
}

__global__ __launch_bounds__(256) void reduce_o(const float* __restrict__ bo, float* __restrict__ out)
{
    size_t base = ((size_t)blockIdx.x * 256 + threadIdx.x) * 4;
    int col = (int)(base & (D_MODEL - 1));
    float4 a = *(const float4*)(g_part + 0 * (size_t)CSLAB + base);
    float4 b = *(const float4*)(g_part + 1 * (size_t)CSLAB + base);
    float4 d = *(const float4*)(g_part + 2 * (size_t)CSLAB + base);
    float4 e = *(const float4*)(g_part + 3 * (size_t)CSLAB + base);
    float4 bb = *(const float4*)(bo + col);
    float4 o;
    o.x = a.x + b.x + d.x + e.x + bb.x;
    o.y = a.y + b.y + d.y + e.y + bb.y;
    o.z = a.z + b.z + d.z + e.z + bb.z;
    o.w = a.w + b.w + d.w + e.w + bb.w;
    *(float4*)(out + base) = o;
}

// ---------------- attention: fp16 2-term tensor-core, one block per (b,h) ----------------
#define SQ 0
#define SS 512
#define SSTR 1032
#define SL (SS + 8 * SSTR)
#define ST (SL + 16)
#define STG_STRIDE 68
#define STAGE_FLOATS (128 * STG_STRIDE)
#define SM_FLOATS (ST + 2 * STAGE_FLOATS)
#define SM_BYTES (SM_FLOATS * 4)

#define CP_COMMIT asm volatile("cp.async.commit_group;\n" ::: "memory")

__device__ __forceinline__ void cp16(uint32_t dst, const float* src)
{
    asm volatile("cp.async.cg.shared.global [%0], [%1], 16;\n" ::"r"(dst), "l"(src));
}

__device__ __forceinline__ void attn_issue(const float* __restrict__ cbase,
                                           const float* __restrict__ nbase,
                                           int c, int tid, uint32_t stg)
{
#pragma unroll
    for (int i = 0; i < 8; i++) {
        int j = tid + (i << 8);
        int sloc = j >> 4, d4 = j & 15;
        int s = c * 128 + sloc;
        const float* src = (s < CACHE_T) ? (cbase + (size_t)s * HEAD_DIM + (d4 << 2))
                                         : (nbase + (size_t)(s - CACHE_T) * D_MODEL + (d4 << 2));
        cp16(stg + (uint32_t)((sloc * STG_STRIDE + (d4 << 2)) * 4), src);
    }
}

__global__ __launch_bounds__(256) void attn_kernel(const float* __restrict__ cacheK,
                                                   const float* __restrict__ cacheV)
{
    extern __shared__ float sm[];
    const int bh = blockIdx.x;
    const int b = bh >> 5, h = bh & 31;
    const int tid = threadIdx.x, lane = tid & 31, wid = tid >> 5;
    const int lr = lane >> 2;
    const int lk = (lane & 3) * 2;

    const uint32_t stg_u32[2] = {
        (uint32_t)__cvta_generic_to_shared(sm + ST),
        (uint32_t)__cvta_generic_to_shared(sm + ST + STAGE_FLOATS)};

#pragma unroll
    for (int i = 0; i < 2; i++) {
        int j = tid + i * 256;
        int t = j >> 6, d = j & 63;
        sm[SQ + j] = 0.125f * g_q[(size_t)(b * TT + t) * D_MODEL + h * HEAD_DIM + d];
    }

    const float* cK = cacheK + (size_t)(b * N_HEADS + h) * CACHE_T * HEAD_DIM;
    const float* cV = cacheV + (size_t)(b * N_HEADS + h) * CACHE_T * HEAD_DIM;
    const float* nK = g_k + (size_t)(b * TT) * D_MODEL + h * HEAD_DIM;
    const float* nV = g_v + (size_t)(b * TT) * D_MODEL + h * HEAD_DIM;

    attn_issue(cK, nK, 0, tid, stg_u32[0]);
    CP_COMMIT;
    __syncthreads();

    // q A-fragments: fp16 hi/lo (rows 8..15 zero)
    uint32_t aqh[4][2], aql[4][2];
    const uint32_t zero = 0;
#pragma unroll
    for (int ks = 0; ks < 4; ks++) {
        float2 q0 = *(const float2*)&sm[SQ + lr * 64 + ks * 16 + lk];
        float2 q1 = *(const float2*)&sm[SQ + lr * 64 + ks * 16 + lk + 8];
        f2_hilo_h(q0, aqh[ks][0], aql[ks][0]);
        f2_hilo_h(q1, aqh[ks][1], aql[ks][1]);
    }

    // ---------- phase A: scores = (qh + ql) . K16 ----------
    for (int c = 0; c < 8; c++) {
        __syncthreads();
        if (c < 7) {
            attn_issue(cK, nK, c + 1, tid, stg_u32[(c + 1) & 1]);
            CP_COMMIT;
            asm volatile("cp.async.wait_group 1;\n" ::: "memory");
        } else {
            asm volatile("cp.async.wait_group 0;\n" ::: "memory");
        }
        __syncthreads();
        const float* stg = sm + ST + (c & 1) * STAGE_FLOATS;

        float cA[2][4];
#pragma unroll
        for (int nt = 0; nt < 2; nt++)
#pragma unroll
            for (int e = 0; e < 4; e++) cA[nt][e] = 0.0f;

#pragma unroll
        for (int ks = 0; ks < 4; ks++) {
            uint32_t kb[2][2];
#pragma unroll
            for (int nt = 0; nt < 2; nt++) {
                int key = wid * 16 + nt * 8 + lr;
                kb[nt][0] = f2_h(*(const float2*)&stg[key * STG_STRIDE + ks * 16 + lk]);
                kb[nt][1] = f2_h(*(const float2*)&stg[key * STG_STRIDE + ks * 16 + lk + 8]);
            }
#pragma unroll
            for (int nt = 0; nt < 2; nt++)
                MMA_F16(cA[nt], aqh[ks][0], zero, aqh[ks][1], zero, kb[nt][0], kb[nt][1]);
#pragma unroll
            for (int nt = 0; nt < 2; nt++)
                MMA_F16(cA[nt], aql[ks][0], zero, aql[ks][1], zero, kb[nt][0], kb[nt][1]);
        }
#pragma unroll
        for (int nt = 0; nt < 2; nt++) {
            int col = c * 128 + wid * 16 + nt * 8 + lk;
            *(float2*)&sm[SS + lr * SSTR + col] = make_float2(cA[nt][0], cA[nt][1]);
        }
    }

    attn_issue(cV, nV, 0, tid, stg_u32[0]);
    CP_COMMIT;
    __syncthreads();

    // ---------- softmax ----------
    {
        const int qi = wid;
        if (qi < 8) {
            float m = -1e30f;
#pragma unroll
            for (int i = 0; i < 32; i++) m = fmaxf(m, sm[SS + qi * SSTR + lane + i * 32]);
#pragma unroll
            for (int off = 16; off >= 1; off >>= 1) m = fmaxf(m, __shfl_xor_sync(0xffffffffu, m, off));
            float ssum = 0.0f;
#pragma unroll
            for (int i = 0; i < 32; i++) {
                int idx = SS + qi * SSTR + lane + i * 32;
                float e = __expf(sm[idx] - m);
                sm[idx] = e;
                ssum += e;
            }
#pragma unroll
            for (int off = 16; off >= 1; off >>= 1) ssum += __shfl_xor_sync(0xffffffffu, ssum, off);
            if (lane == 0) sm[SL + qi] = 1.0f / ssum;
        }
    }
    __syncthreads();

    // ---------- phase B: out = (Ph + Pl) . V16 ----------
    float cav[8][4];
#pragma unroll
    for (int nt = 0; nt < 8; nt++)
#pragma unroll
        for (int e = 0; e < 4; e++) cav[nt][e] = 0.0f;

    for (int c = 0; c < 8; c++) {
        __syncthreads();
        if (c < 7) {
            attn_issue(cV, nV, c + 1, tid, stg_u32[(c + 1) & 1]);
            CP_COMMIT;
            asm volatile("cp.async.wait_group 1;\n" ::: "memory");
        } else {
            asm volatile("cp.async.wait_group 0;\n" ::: "memory");
        }
        __syncthreads();
        const float* stg = sm + ST + (c & 1) * STAGE_FLOATS;

        float2 p0 = *(const float2*)&sm[SS + lr * SSTR + c * 128 + wid * 16 + lk];
        float2 p1 = *(const float2*)&sm[SS + lr * SSTR + c * 128 + wid * 16 + lk + 8];
        uint32_t pah0, pal0, pah2, pal2;
        f2_hilo_h(p0, pah0, pal0);
        f2_hilo_h(p1, pah2, pal2);

        const int kb = wid * 16;
        uint32_t vb[8][2];
#pragma unroll
        for (int nt = 0; nt < 8; nt++) {
            int n = nt * 8 + lr;
            float v0 = stg[(kb + lk + 0) * STG_STRIDE + n];
            float v1 = stg[(kb + lk + 1) * STG_STRIDE + n];
            float v8 = stg[(kb + lk + 8) * STG_STRIDE + n];
            float v9 = stg[(kb + lk + 9) * STG_STRIDE + n];
            vb[nt][0] = f2_h(make_float2(v0, v1));
            vb[nt][1] = f2_h(make_float2(v8, v9));
        }
#pragma unroll
        for (int nt = 0; nt < 8; nt++)
            MMA_F16(cav[nt], pah0, zero, pah2, zero, vb[nt][0], vb[nt][1]);
#pragma unroll
        for (int nt = 0; nt < 8; nt++)
            MMA_F16(cav[nt], pal0, zero, pal2, zero, vb[nt][0], vb[nt][1]);
    }
    __syncthreads();

#pragma unroll
    for (int nt = 0; nt < 8; nt++)
        *(float2*)&sm[ST + wid * 544 + lr * STG_STRIDE + nt * 8 + lk] =
            make_float2(cav[nt][0], cav[nt][1]);
    __syncthreads();
#pragma unroll
    for (int r = 0; r < 2; r++) {
        int o = tid + r * 256;
        int qi = o >> 6, d = o & 63;
        float s = 0.0f;
#pragma unroll
        for (int gg = 0; gg < 8; gg++) s += sm[ST + gg * 544 + qi * STG_STRIDE + d];
        g_ao[(size_t)(b * TT + qi) * D_MODEL + h * HEAD_DIM + d] = s * sm[SL + qi];
    }
}

// ---------------- launch ----------------
extern "C" void kernel_launch(void* const* d_in, const int* in_sizes, int n_in,
                              void* d_out, int out_size)
{
    const float* x  = (const float*)d_in[0];
    const float* cK = (const float*)d_in[1];
    const float* cV = (const float*)d_in[2];
    const float* Wq = (const float*)d_in[3];
    const float* bq = (const float*)d_in[4];
    const float* Wk = (const float*)d_in[5];
    const float* bk = (const float*)d_in[6];
    const float* Wv = (const float*)d_in[7];
    const float* bv = (const float*)d_in[8];
    const float* Wo = (const float*)d_in[9];
    const float* bo = (const float*)d_in[10];
    float* out = (float*)d_out;

    cudaFuncSetAttribute((const void*)attn_kernel,
                         cudaFuncAttributeMaxDynamicSharedMemorySize, SM_BYTES);
    cudaFuncSetAttribute((const void*)gemm_kernel<3>,
                         cudaFuncAttributeMaxDynamicSharedMemorySize, GEMM_SMEM);
    cudaFuncSetAttribute((const void*)gemm_kernel<4>,
                         cudaFuncAttributeMaxDynamicSharedMemorySize, GEMM_SMEM);
    (void)cudaGetLastError();

    gemm_kernel<3><<<dim3(16, 2, 9), 512, GEMM_SMEM>>>(x, Wq, Wk, Wv, 0);
    reduce_qkv<<<dim3(512, 3), 256>>>(bq, bk, bv);

    attn_kernel<<<N_HEADS * 32, 256, SM_BYTES>>>(cK, cV);

    gemm_kernel<4><<<dim3(16, 2, 4), 512, GEMM_SMEM>>>(x, Wo, Wo, Wo, 1);
    reduce_o<<<512, 256>>>(bo, out);
}